// round 9
// baseline (speedup 1.0000x reference)
#include <cuda_runtime.h>
#include <cuda_fp16.h>
#include <cuda_bf16.h>
#include <cstdint>

#define NN 100000
#define DD 128
#define GG 64

// Scratch (__device__ globals; no allocation allowed)
__device__ __align__(16) __half g_xh[NN * DD];     // x * cs, fp16
__device__ __align__(16) __half g_h0[NN * DD];     // layer outputs (fp16)
__device__ __align__(16) __half g_h1[NN * DD];
__device__ __align__(16) __half g_h2[NN * DD];
__device__ __align__(16) __half g_agg[NN * DD];    // gathered+cd-scaled rows (fp16)
__device__ __align__(16) __half g_wt[3 * DD * DD]; // W transposed + fp16: wt[l][n][k]
__device__ float g_cs[NN];
__device__ float g_cd[NN];
__device__ int   g_degout[NN];
__device__ int   g_degin[NN];
__device__ int   g_rowstart[NN];
__device__ int   g_cursor[NN];
__device__ int   g_csr[1700000];
__device__ __align__(16) float g_sums[GG * DD];
__device__ float g_cnt[GG];

// ---------------------------------------------------------------------------
// Setup: zero int arrays + pool accumulators, prep all 3 W (transpose + fp16)
// ---------------------------------------------------------------------------
__global__ void setup_kernel(const float* __restrict__ W0, const float* __restrict__ W1,
                             const float* __restrict__ W2, int n) {
    int i = blockIdx.x * blockDim.x + threadIdx.x;
    if (i < n) { g_degout[i] = 0; g_degin[i] = 0; g_cursor[i] = 0; }
    if (i < 3 * DD * DD) {
        const float* W = (i < DD * DD) ? W0 : ((i < 2 * DD * DD) ? W1 : W2);
        int j = i & (DD * DD - 1);
        int k = j >> 7, nn = j & 127;
        g_wt[(i >> 14) * DD * DD + nn * DD + k] = __float2half(W[j]);
    }
    if (i < GG * DD) g_sums[i] = 0.0f;
    if (i < GG) g_cnt[i] = 0.0f;
}

// 4 edges per thread; counting atomics have unused returns -> RED (no return trip)
__global__ void count_deg_kernel(const int* __restrict__ src,
                                 const int* __restrict__ dst, int e) {
    int i = (blockIdx.x * blockDim.x + threadIdx.x) * 4;
    if (i + 4 <= e) {
        int4 s = *(const int4*)(src + i);
        int4 d = *(const int4*)(dst + i);
        atomicAdd(&g_degout[s.x], 1); atomicAdd(&g_degin[d.x], 1);
        atomicAdd(&g_degout[s.y], 1); atomicAdd(&g_degin[d.y], 1);
        atomicAdd(&g_degout[s.z], 1); atomicAdd(&g_degin[d.z], 1);
        atomicAdd(&g_degout[s.w], 1); atomicAdd(&g_degin[d.w], 1);
    } else {
        for (; i < e; i++) {
            atomicAdd(&g_degout[src[i]], 1);
            atomicAdd(&g_degin[dst[i]], 1);
        }
    }
}

// Single-CTA scan over degin -> rowstart, plus norms. 1024 threads.
__global__ void norm_scan_kernel(int n) {
    __shared__ int s[1024];
    int t = threadIdx.x;
    int chunk = (n + 1023) >> 10;
    int lo = min(t * chunk, n), hi = min(lo + chunk, n);
    int sum = 0;
    for (int i = lo; i < hi; i++) sum += g_degin[i];
    s[t] = sum;
    __syncthreads();
#pragma unroll
    for (int off = 1; off < 1024; off <<= 1) {
        int add = (t >= off) ? s[t - off] : 0;
        __syncthreads();
        s[t] += add;
        __syncthreads();
    }
    int run = s[t] - sum;   // exclusive
    for (int i = lo; i < hi; i++) { g_rowstart[i] = run; run += g_degin[i]; }
    for (int i = t; i < n; i += 1024) {
        g_cs[i] = rsqrtf((float)(g_degout[i] + 1));
        g_cd[i] = rsqrtf((float)(g_degin[i] + 1));
    }
}

// 4 edges per thread: 4 independent atomic->store chains in flight
__global__ void fill_csr_kernel(const int* __restrict__ src,
                                const int* __restrict__ dst, int e) {
    int i = (blockIdx.x * blockDim.x + threadIdx.x) * 4;
    if (i + 4 <= e) {
        int4 s = *(const int4*)(src + i);
        int4 d = *(const int4*)(dst + i);
        int p0 = atomicAdd(&g_cursor[d.x], 1);
        int p1 = atomicAdd(&g_cursor[d.y], 1);
        int p2 = atomicAdd(&g_cursor[d.z], 1);
        int p3 = atomicAdd(&g_cursor[d.w], 1);
        int r0 = __ldg(&g_rowstart[d.x]);
        int r1 = __ldg(&g_rowstart[d.y]);
        int r2 = __ldg(&g_rowstart[d.z]);
        int r3 = __ldg(&g_rowstart[d.w]);
        g_csr[r0 + p0] = s.x;
        g_csr[r1 + p1] = s.y;
        g_csr[r2 + p2] = s.z;
        g_csr[r3 + p3] = s.w;
    } else {
        for (; i < e; i++) {
            int d = dst[i];
            int pos = atomicAdd(&g_cursor[d], 1);
            g_csr[g_rowstart[d] + pos] = src[i];
        }
    }
}

// xh[node] = half(x[node] * cs[node]); one thread per float4 quad
__global__ void prep_x_kernel(const float* __restrict__ x, int n) {
    int i = blockIdx.x * blockDim.x + threadIdx.x;
    if (i >= n * 32) return;
    int node = i >> 5, q = i & 31;
    float c = g_cs[node];
    float4 v = __ldg((const float4*)x + (size_t)node * 32 + q);
    uint2 o;
    *(__half2*)&o.x = __float22half2_rn(make_float2(v.x * c, v.y * c));
    *(__half2*)&o.y = __float22half2_rn(make_float2(v.z * c, v.w * c));
    ((uint2*)g_xh)[(size_t)node * 32 + q] = o;
}

// ---------------------------------------------------------------------------
// Gather: agg[node] = half( cd[node] * ( hs[node] + sum_in hs[src] ) )
// One warp per node. Lanes split 16+16: each half-warp covers a full 256B row
// (uint4 = 16B per lane), the two halves process even/odd edges concurrently.
// Cross-half shfl_xor(16) reduction at the end. Unroll 8 -> 16 edges in flight.
// ---------------------------------------------------------------------------
__device__ __forceinline__ void acc8(float* acc, uint4 v) {
    float2 a0 = __half22float2(*(__half2*)&v.x);
    float2 a1 = __half22float2(*(__half2*)&v.y);
    float2 a2 = __half22float2(*(__half2*)&v.z);
    float2 a3 = __half22float2(*(__half2*)&v.w);
    acc[0] += a0.x; acc[1] += a0.y; acc[2] += a1.x; acc[3] += a1.y;
    acc[4] += a2.x; acc[5] += a2.y; acc[6] += a3.x; acc[7] += a3.y;
}

__global__ void __launch_bounds__(256)
gather_kernel(const __half* __restrict__ h, int n) {
    int w = (blockIdx.x * blockDim.x + threadIdx.x) >> 5;
    int lane = threadIdx.x & 31;
    int lane16 = lane & 15;
    int hf = lane >> 4;
    if (w >= n) return;
    int node = w;
    int base = g_rowstart[node];
    int deg  = g_degin[node];

    float acc[8];
#pragma unroll
    for (int q = 0; q < 8; q++) acc[q] = 0.0f;
    if (hf == 0) {
        uint4 v = __ldg((const uint4*)(h + (size_t)node * DD) + lane16);
        acc8(acc, v);
    }

    for (int j0 = 0; j0 < deg; j0 += 32) {
        int cnt = min(32, deg - j0);
        int sj = (lane < cnt) ? __ldg(&g_csr[base + j0 + lane]) : 0;
        int k = 0;
        for (; k + 16 <= cnt; k += 16) {
            uint4 v[8];
#pragma unroll
            for (int u = 0; u < 8; u++) {
                int s = __shfl_sync(0xffffffffu, sj, k + 2 * u + hf);
                v[u] = __ldg((const uint4*)(h + (size_t)s * DD) + lane16);
            }
#pragma unroll
            for (int u = 0; u < 8; u++) acc8(acc, v[u]);
        }
        for (; k + 2 <= cnt; k += 2) {
            int s = __shfl_sync(0xffffffffu, sj, k + hf);
            uint4 v = __ldg((const uint4*)(h + (size_t)s * DD) + lane16);
            acc8(acc, v);
        }
        if (k < cnt) {
            int s = __shfl_sync(0xffffffffu, sj, k);
            if (hf == 0) {
                uint4 v = __ldg((const uint4*)(h + (size_t)s * DD) + lane16);
                acc8(acc, v);
            }
        }
    }

    float cdv = g_cd[node];
#pragma unroll
    for (int q = 0; q < 8; q++) {
        acc[q] += __shfl_xor_sync(0xffffffffu, acc[q], 16);
        acc[q] *= cdv;
    }
    if (hf == 0) {
        uint4 o;
        *(__half2*)&o.x = __float22half2_rn(make_float2(acc[0], acc[1]));
        *(__half2*)&o.y = __float22half2_rn(make_float2(acc[2], acc[3]));
        *(__half2*)&o.z = __float22half2_rn(make_float2(acc[4], acc[5]));
        *(__half2*)&o.w = __float22half2_rn(make_float2(acc[6], acc[7]));
        ((uint4*)(g_agg + (size_t)node * DD))[lane16] = o;
    }
}

// ---------------------------------------------------------------------------
// Tensor-core GEMM, fp16 inputs / fp32 accum (mma.sync m16n8k16).
// out = half( relu(agg @ W + b) [* cs[row]] ). One CTA per 128 rows, 8 warps
// each 32(M)x64(N). Smem stride 136 halfs -> conflict-free fragment loads.
// ---------------------------------------------------------------------------
#define ASTR 136
#define GT_SMEM (2 * 128 * ASTR * 2)

__global__ void __launch_bounds__(256, 1)
gemm_mma_kernel(const __half* __restrict__ wt, const float* __restrict__ b,
                __half* __restrict__ out, int n, int cs_out) {
    extern __shared__ __half sh[];
    __half* Bsm = sh;               // 128 x ASTR : Wt[n][k]
    __half* Asm = sh + 128 * ASTR;  // 128 x ASTR : A[m][k]

    int t = threadIdx.x;
    int rows0 = blockIdx.x * 128;

#pragma unroll
    for (int it = 0; it < 8; it++) {
        int idx = t + it * 256;
        int r = idx >> 4, c = idx & 15;
        *(uint4*)&Bsm[r * ASTR + c * 8] = __ldg((const uint4*)wt + idx);
    }
#pragma unroll
    for (int it = 0; it < 8; it++) {
        int idx = t + it * 256;
        int r = idx >> 4, c = idx & 15;
        int gr = rows0 + r;
        if (gr > n - 1) gr = n - 1;
        *(uint4*)&Asm[r * ASTR + c * 8] = __ldg((const uint4*)(g_agg + (size_t)gr * DD) + c);
    }
    __syncthreads();

    int wid = t >> 5, lane = t & 31;
    int groupID = lane >> 2, ktid = lane & 3;
    int warpM = (wid & 3) * 32;
    int warpN = (wid >> 2) * 64;

    float acc[2][8][4];
#pragma unroll
    for (int mt = 0; mt < 2; mt++)
#pragma unroll
        for (int nt = 0; nt < 8; nt++)
#pragma unroll
            for (int q = 0; q < 4; q++) acc[mt][nt][q] = 0.0f;

#pragma unroll
    for (int k0 = 0; k0 < 128; k0 += 16) {
        uint32_t a[2][4];
#pragma unroll
        for (int mt = 0; mt < 2; mt++) {
            int r0 = warpM + mt * 16 + groupID;
            a[mt][0] = *(const uint32_t*)&Asm[r0 * ASTR + k0 + ktid * 2];
            a[mt][1] = *(const uint32_t*)&Asm[(r0 + 8) * ASTR + k0 + ktid * 2];
            a[mt][2] = *(const uint32_t*)&Asm[r0 * ASTR + k0 + ktid * 2 + 8];
            a[mt][3] = *(const uint32_t*)&Asm[(r0 + 8) * ASTR + k0 + ktid * 2 + 8];
        }
#pragma unroll
        for (int nt = 0; nt < 8; nt++) {
            int c0 = warpN + nt * 8 + groupID;
            uint32_t b0 = *(const uint32_t*)&Bsm[c0 * ASTR + k0 + ktid * 2];
            uint32_t b1 = *(const uint32_t*)&Bsm[c0 * ASTR + k0 + ktid * 2 + 8];
#pragma unroll
            for (int mt = 0; mt < 2; mt++) {
                asm volatile(
                    "mma.sync.aligned.m16n8k16.row.col.f32.f16.f16.f32 "
                    "{%0,%1,%2,%3}, {%4,%5,%6,%7}, {%8,%9}, {%0,%1,%2,%3};"
                    : "+f"(acc[mt][nt][0]), "+f"(acc[mt][nt][1]),
                      "+f"(acc[mt][nt][2]), "+f"(acc[mt][nt][3])
                    : "r"(a[mt][0]), "r"(a[mt][1]), "r"(a[mt][2]), "r"(a[mt][3]),
                      "r"(b0), "r"(b1));
            }
        }
    }

#pragma unroll
    for (int mt = 0; mt < 2; mt++) {
        int r0 = rows0 + warpM + mt * 16 + groupID;
        int r1 = r0 + 8;
        float sc0 = 1.0f, sc1 = 1.0f;
        if (cs_out) {
            if (r0 < n) sc0 = g_cs[r0];
            if (r1 < n) sc1 = g_cs[r1];
        }
#pragma unroll
        for (int nt = 0; nt < 8; nt++) {
            int col = warpN + nt * 8 + 2 * ktid;
            float2 bb = __ldg((const float2*)(b + col));
            if (r0 < n) {
                float2 o = make_float2(fmaxf(acc[mt][nt][0] + bb.x, 0.0f) * sc0,
                                       fmaxf(acc[mt][nt][1] + bb.y, 0.0f) * sc0);
                *(__half2*)(out + (size_t)r0 * DD + col) = __float22half2_rn(o);
            }
            if (r1 < n) {
                float2 o = make_float2(fmaxf(acc[mt][nt][2] + bb.x, 0.0f) * sc1,
                                       fmaxf(acc[mt][nt][3] + bb.y, 0.0f) * sc1);
                *(__half2*)(out + (size_t)r1 * DD + col) = __float22half2_rn(o);
            }
        }
    }
}

// ---------------------------------------------------------------------------
// Pooling: graph_ids sorted -> run-based accumulation, flush per run.
// ---------------------------------------------------------------------------
__global__ void pool_kernel(const __half* __restrict__ h,
                            const int* __restrict__ gid, int n) {
    int w = (blockIdx.x * blockDim.x + threadIdx.x) >> 5;
    int lane = threadIdx.x & 31;
    int n0 = w * 16;
    if (n0 >= n) return;
    int n1 = min(n0 + 16, n);

    float4 acc = make_float4(0.f, 0.f, 0.f, 0.f);
    int curg = gid[n0];
    int cnt = 0;
    for (int node = n0; node < n1; node++) {
        int g = gid[node];
        if (g != curg) {
            float* o = g_sums + curg * DD + lane * 4;
            asm volatile("red.global.add.v4.f32 [%0], {%1, %2, %3, %4};"
                         :: "l"(o), "f"(acc.x), "f"(acc.y), "f"(acc.z), "f"(acc.w)
                         : "memory");
            if (lane == 0) atomicAdd(&g_cnt[curg], (float)cnt);
            acc = make_float4(0.f, 0.f, 0.f, 0.f);
            curg = g; cnt = 0;
        }
        uint2 v = __ldg((const uint2*)h + (size_t)node * 32 + lane);
        float2 a0 = __half22float2(*(__half2*)&v.x);
        float2 a1 = __half22float2(*(__half2*)&v.y);
        acc.x += a0.x; acc.y += a0.y; acc.z += a1.x; acc.w += a1.y;
        cnt++;
    }
    float* o = g_sums + curg * DD + lane * 4;
    asm volatile("red.global.add.v4.f32 [%0], {%1, %2, %3, %4};"
                 :: "l"(o), "f"(acc.x), "f"(acc.y), "f"(acc.z), "f"(acc.w)
                 : "memory");
    if (lane == 0) atomicAdd(&g_cnt[curg], (float)cnt);
}

__global__ void divide_kernel(float* __restrict__ out) {
    int i = blockIdx.x * blockDim.x + threadIdx.x;
    if (i < GG * DD) out[i] = g_sums[i] / fmaxf(g_cnt[i >> 7], 1.0f);
}

// ---------------------------------------------------------------------------
extern "C" void kernel_launch(void* const* d_in, const int* in_sizes, int n_in,
                              void* d_out, int out_size) {
    const float* x  = (const float*)d_in[0];
    const float* Ws[3] = {(const float*)d_in[1], (const float*)d_in[3], (const float*)d_in[5]};
    const float* bs[3] = {(const float*)d_in[2], (const float*)d_in[4], (const float*)d_in[6]};
    const int* src = (const int*)d_in[7];
    const int* dst = (const int*)d_in[8];
    const int* gid = (const int*)d_in[9];

    int n = in_sizes[0] / DD;          // 100000
    int e = in_sizes[7];               // 1600000

    cudaFuncSetAttribute(gemm_mma_kernel,
                         cudaFuncAttributeMaxDynamicSharedMemorySize, GT_SMEM);

    void* pxh; cudaGetSymbolAddress(&pxh, g_xh);
    void* p0;  cudaGetSymbolAddress(&p0, g_h0);
    void* p1;  cudaGetSymbolAddress(&p1, g_h1);
    void* p2;  cudaGetSymbolAddress(&p2, g_h2);
    void* pw;  cudaGetSymbolAddress(&pw, g_wt);
    __half* xh = (__half*)pxh;
    __half* h0 = (__half*)p0;
    __half* h1 = (__half*)p1;
    __half* h2 = (__half*)p2;
    __half* wt = (__half*)pw;

    int e4blocks = ((e + 3) / 4 + 255) / 256;
    setup_kernel<<<(n + 255) / 256, 256>>>(Ws[0], Ws[1], Ws[2], n);
    count_deg_kernel<<<e4blocks, 256>>>(src, dst, e);
    norm_scan_kernel<<<1, 1024>>>(n);
    fill_csr_kernel<<<e4blocks, 256>>>(src, dst, e);
    prep_x_kernel<<<(int)(((size_t)n * 32 + 255) / 256), 256>>>(x, n);

    int gtiles = (n + 127) / 128;
    int gblocks = (int)(((size_t)n * 32 + 255) / 256);

    gather_kernel<<<gblocks, 256>>>(xh, n);
    gemm_mma_kernel<<<gtiles, 256, GT_SMEM>>>(wt, bs[0], h0, n, 1);
    gather_kernel<<<gblocks, 256>>>(h0, n);
    gemm_mma_kernel<<<gtiles, 256, GT_SMEM>>>(wt + DD * DD, bs[1], h1, n, 1);
    gather_kernel<<<gblocks, 256>>>(h1, n);
    gemm_mma_kernel<<<gtiles, 256, GT_SMEM>>>(wt + 2 * DD * DD, bs[2], h2, n, 0);

    pool_kernel<<<(n + 127) / 128, 256>>>(h2, gid, n);
    divide_kernel<<<(GG * DD + 255) / 256, 256>>>((float*)d_out);
}